// round 12
// baseline (speedup 1.0000x reference)
#include <cuda_runtime.h>
#include <cuda_fp16.h>
#include <string.h>

// Problem constants
#define B_TOTAL 65536
#define CN 16
#define CC 16
#define DIM 128
#define VOC 65
#define EPSF 1e-5f

// Decomposition: D=128 in 2 chunks of 64. One warp handles TWO rows per
// iteration: lanes 0-15 -> row A, lanes 16-31 -> row B. Each lane owns an
// 8B fp16 slice of its row's 64-wide chunk.
// Table lives in a global fp16 mirror (L1D-cached, 130KB/SM sector footprint).
// Slots are PACKED: one 32-bit word per attr = {fp16(z) << 16 | v}.
#define DCH 64
#define NCHUNK 2
#define NBX 74            // 74 * 2 = 148 CTAs = one per SM
#define NTHREADS 1024
#define NWARPS 32

#define EMB_VALS (CC * VOC * DIM)   // 133120 fp16 values = 266240 B mirror
#define ATTR_STRIDE (VOC * DIM * 2) // 16640 B per attr in the mirror

__device__ __half2 d_emb16[EMB_VALS / 2];   // fp16 mirror of emb, full D

// ---- Kernel 0: convert emb fp32 -> fp16 mirror (runs every launch) ----
__global__ void convert_emb_kernel(const float* __restrict__ emb) {
    int i = blockIdx.x * blockDim.x + threadIdx.x;
    if (i < EMB_VALS / 2) {
        float2 f = *(const float2*)(emb + 2 * i);
        d_emb16[i] = __floats2half2_rn(f.x, f.y);
    }
}

__device__ __forceinline__ __half2 u2h2(unsigned u) {
    __half2 h; memcpy(&h, &u, 4); return h;
}

__global__ __launch_bounds__(NTHREADS, 1)
void embed_att_kernel(const float* __restrict__ x_num,
                      const float* __restrict__ means,
                      const float* __restrict__ stds,
                      const float* __restrict__ lin_W,
                      const float* __restrict__ lin_b,
                      const int*   __restrict__ x_cat,
                      float*       __restrict__ out)
{
    // Packed slot buffers: per warp 2 bufs x 128 B = 256 B -> 8 KB total.
    __shared__ __align__(16) char slots[NWARPS * 256];

    const int tid   = threadIdx.x;
    const int lane  = tid & 31;
    const int wrp   = tid >> 5;
    const int sub   = lane & 15;   // attr index (producer) / 8B slice owner
    const int grp   = lane >> 4;   // 0 = row A, 1 = row B
    const int chunk = blockIdx.y;
    const int dbase = chunk * DCH;

    // ---- Per-lane constants (0.5 folded for tanh-sigmoid) ----
    const float invr2 = 0.5f / (stds[sub] + EPSF);
    const float c02   = -means[sub] * invr2;

    // W slice (4 floats per attr) as 2x half2; bias pre-summed in fp32
    __half2 wa[CN], wb[CN];
    float4 bias = make_float4(0.f, 0.f, 0.f, 0.f);
    #pragma unroll
    for (int i = 0; i < CN; i++) {
        float4 wf = *(const float4*)(lin_W + i * DIM + dbase + 4 * sub);
        wa[i] = __floats2half2_rn(wf.x, wf.y);
        wb[i] = __floats2half2_rn(wf.z, wf.w);
        float4 lb = *(const float4*)(lin_b + i * DIM + dbase + 4 * sub);
        bias.x += lb.x; bias.y += lb.y; bias.z += lb.z; bias.w += lb.w;
    }

    // ---- Balanced row range ----
    const int bx    = blockIdx.x;
    const int start = (int)(((long long)bx       * B_TOTAL) / NBX);
    const int end   = (int)(((long long)(bx + 1) * B_TOTAL) / NBX);

    char* wslot = slots + wrp * 256;
    // Lane's gather base inside the fp16 mirror: chunk half + 8B slice.
    const char* myemb = (const char*)d_emb16 + chunk * (DCH * 2) + 8 * sub;
    int buf = 0;

    const __half2 h2z = __float2half2_rn(0.f);

    for (int b = start + wrp * 2; b < end; b += 2 * NWARPS) {
        const int  myrow = b + grp;
        const bool valid = myrow < end;

        // ---- Produce: packed word {fp16(z)<<16 | v} for (myrow, sub) ----
        float x = 0.f; int v = 0;
        if (valid) {
            x = __ldcs(x_num + myrow * CN + sub);
            v = __ldcs(x_cat + myrow * CC + sub);
        }
        float t = fmaf(x, invr2, c02);
        float th;
        asm("tanh.approx.f32 %0, %1;" : "=f"(th) : "f"(t));
        float z = fmaf(th, 0.5f, 0.5f);          // sigmoid(2t) = 0.5*tanh(t)+0.5
        unsigned zb = (unsigned)__half_as_ushort(__float2half_rn(z));
        unsigned word = __byte_perm((unsigned)v, zb, 0x5410);  // {z.hi16 | v.lo16}
        *(unsigned*)(wslot + buf * 128 + grp * 64 + sub * 4) = word;
        __syncwarp();

        // ---- Consume: 4 batches of {1 slot LDS.128 -> 4 LDG gathers} ----
        const char* sl = wslot + buf * 128 + grp * 64;
        __half2 a0 = h2z, b0 = h2z, a1 = h2z, b1 = h2z;  // gather chains
        __half2 n0 = h2z, n1 = h2z;                       // numeric chains
        #pragma unroll
        for (int h = 0; h < 4; h++) {
            uint4 s = *(const uint4*)(sl + h * 16);       // 4 packed attrs
            // gather addresses (attr base folds into LDG immediate)
            const char* base = myemb + 4 * h * ATTR_STRIDE;
            uint2 q0 = __ldg((const uint2*)(base + 0 * ATTR_STRIDE + ((s.x & 0xFFFFu) << 8)));
            uint2 q1 = __ldg((const uint2*)(base + 1 * ATTR_STRIDE + ((s.y & 0xFFFFu) << 8)));
            uint2 q2 = __ldg((const uint2*)(base + 2 * ATTR_STRIDE + ((s.z & 0xFFFFu) << 8)));
            uint2 q3 = __ldg((const uint2*)(base + 3 * ATTR_STRIDE + ((s.w & 0xFFFFu) << 8)));
            // z splats (PRMT: duplicate high 16 bits)
            __half2 z0 = u2h2(__byte_perm(s.x, s.x, 0x3232));
            __half2 z1 = u2h2(__byte_perm(s.y, s.y, 0x3232));
            __half2 z2 = u2h2(__byte_perm(s.z, s.z, 0x3232));
            __half2 z3 = u2h2(__byte_perm(s.w, s.w, 0x3232));
            // numeric FMA chains (independent of gather results)
            n0 = __hfma2(z0, wa[4 * h + 0], n0); n1 = __hfma2(z0, wb[4 * h + 0], n1);
            n0 = __hfma2(z1, wa[4 * h + 1], n0); n1 = __hfma2(z1, wb[4 * h + 1], n1);
            n0 = __hfma2(z2, wa[4 * h + 2], n0); n1 = __hfma2(z2, wb[4 * h + 2], n1);
            n0 = __hfma2(z3, wa[4 * h + 3], n0); n1 = __hfma2(z3, wb[4 * h + 3], n1);
            // gather accumulation: 2 chains per output pair
            a0 = __hadd2(a0, u2h2(q0.x)); a1 = __hadd2(a1, u2h2(q0.y));
            b0 = __hadd2(b0, u2h2(q1.x)); b1 = __hadd2(b1, u2h2(q1.y));
            a0 = __hadd2(a0, u2h2(q2.x)); a1 = __hadd2(a1, u2h2(q2.y));
            b0 = __hadd2(b0, u2h2(q3.x)); b1 = __hadd2(b1, u2h2(q3.y));
        }

        __half2 s0 = __hadd2(__hadd2(a0, b0), n0);
        __half2 s1 = __hadd2(__hadd2(a1, b1), n1);
        float2 f0 = __half22float2(s0);
        float2 f1 = __half22float2(s1);
        if (valid) {
            float4 o = make_float4(bias.x + f0.x, bias.y + f0.y,
                                   bias.z + f1.x, bias.w + f1.y);
            __stcs((float4*)(out + (size_t)myrow * DIM + dbase + 4 * sub), o);
        }
        buf ^= 1;
    }
}

extern "C" void kernel_launch(void* const* d_in, const int* in_sizes, int n_in,
                              void* d_out, int out_size)
{
    const float* x_num = (const float*)d_in[0];
    const float* means = (const float*)d_in[1];
    const float* stds  = (const float*)d_in[2];
    const float* lin_W = (const float*)d_in[3];
    const float* lin_b = (const float*)d_in[4];
    const float* emb   = (const float*)d_in[5];
    const int*   x_cat = (const int*)d_in[6];
    float* out = (float*)d_out;

    // Kernel 0: refresh the fp16 mirror (deterministic, graph-capturable).
    convert_emb_kernel<<<(EMB_VALS / 2 + 255) / 256, 256>>>(emb);

    // Kernel 1: main fused kernel.
    dim3 grid(NBX, NCHUNK);
    embed_att_kernel<<<grid, NTHREADS>>>(
        x_num, means, stds, lin_W, lin_b, x_cat, out);
}